// round 1
// baseline (speedup 1.0000x reference)
#include <cuda_runtime.h>

#define H_   8
#define N_   4096
#define FIN_ 512
#define HD_  64
#define FOUT_ 512

// Scratch (no cudaMalloc allowed): Q/K/V [H][N][HD], Hcat [N][H*HD]
__device__ float g_Q[H_ * N_ * HD_];
__device__ float g_K[H_ * N_ * HD_];
__device__ float g_V[H_ * N_ * HD_];
__device__ float g_Hcat[N_ * H_ * HD_];

// ---------------------------------------------------------------------------
// Kernel 1: QKV projection.  C[h][n][d] = sum_f X[h][n][f] * W[h][d][f]
// Tiled 64x64 NT-GEMM, 256 threads, 4x4 per thread.
// grid = (N/64, 3, H);  blockIdx.y selects Q/K/V.
// ---------------------------------------------------------------------------
__global__ void qkv_kernel(const float* __restrict__ X,
                           const float* __restrict__ Wq,
                           const float* __restrict__ Wk,
                           const float* __restrict__ Wv) {
    const int h     = blockIdx.z;
    const int which = blockIdx.y;
    const int n0    = blockIdx.x * 64;

    const float* W   = (which == 0) ? Wq : (which == 1) ? Wk : Wv;
    float*       Out = (which == 0) ? g_Q : (which == 1) ? g_K : g_V;
    const float* A   = X + (size_t)h * N_ * FIN_;
    W += (size_t)h * HD_ * FIN_;

    __shared__ float As[64][17];
    __shared__ float Bs[64][17];

    const int tx = threadIdx.x & 15;
    const int ty = threadIdx.x >> 4;
    const int lr = threadIdx.x >> 2;          // 0..63
    const int lc = (threadIdx.x & 3) << 2;    // 0,4,8,12

    float acc[4][4];
#pragma unroll
    for (int i = 0; i < 4; i++)
#pragma unroll
        for (int j = 0; j < 4; j++) acc[i][j] = 0.f;

    for (int k0 = 0; k0 < FIN_; k0 += 16) {
        float4 av = *(const float4*)(A + (size_t)(n0 + lr) * FIN_ + k0 + lc);
        float4 bv = *(const float4*)(W + (size_t)lr * FIN_ + k0 + lc);
        As[lr][lc] = av.x; As[lr][lc + 1] = av.y; As[lr][lc + 2] = av.z; As[lr][lc + 3] = av.w;
        Bs[lr][lc] = bv.x; Bs[lr][lc + 1] = bv.y; Bs[lr][lc + 2] = bv.z; Bs[lr][lc + 3] = bv.w;
        __syncthreads();
#pragma unroll
        for (int kk = 0; kk < 16; kk++) {
            float a[4], b[4];
#pragma unroll
            for (int i = 0; i < 4; i++) a[i] = As[ty * 4 + i][kk];
#pragma unroll
            for (int j = 0; j < 4; j++) b[j] = Bs[tx * 4 + j][kk];
#pragma unroll
            for (int i = 0; i < 4; i++)
#pragma unroll
                for (int j = 0; j < 4; j++) acc[i][j] += a[i] * b[j];
        }
        __syncthreads();
    }

#pragma unroll
    for (int i = 0; i < 4; i++)
#pragma unroll
        for (int j = 0; j < 4; j++)
            Out[((size_t)h * N_ + n0 + ty * 4 + i) * HD_ + tx * 4 + j] = acc[i][j];
}

// ---------------------------------------------------------------------------
// Kernel 2: flash attention per (64-query tile, head).
// 256 threads = 8 warps; each warp owns 8 query rows (full 64 dims).
// Per warp: keys split as lane, lane+32.  Online softmax with -1e30 sentinel
// (matches reference NEG_INF semantics exactly, incl. fully-masked rows).
// Writes result directly into concat layout g_Hcat[n][h*64 + d].
// ---------------------------------------------------------------------------
__global__ void attn_kernel(const int* __restrict__ mask) {
    const int h    = blockIdx.y;
    const int q0   = blockIdx.x * 64;
    const int warp = threadIdx.x >> 5;
    const int lane = threadIdx.x & 31;

    extern __shared__ float sm[];
    float* Qs = sm;                 // [64][64]   (broadcast reads only)
    float* Ks = Qs + 64 * 64;       // [64][65]   (pad 65 -> conflict-free col reads)
    float* Vs = Ks + 64 * 65;       // [64][64]   ([key][dim], dim reads conflict-free)
    float* Ps = Vs + 64 * 64;       // [8 warps][8 rows][64 keys]
    float* Pw = Ps + warp * (8 * 64);

    // Load Q tile (contiguous copy since HD == 64)
    const float* Qg = g_Q + ((size_t)h * N_ + q0) * HD_;
    for (int i = threadIdx.x; i < 64 * 64; i += 256) Qs[i] = Qg[i];

    float mrow[8], lrow[8], O0[8], O1[8];
#pragma unroll
    for (int r = 0; r < 8; r++) { mrow[r] = -1e30f; lrow[r] = 0.f; O0[r] = 0.f; O1[r] = 0.f; }

    const int* maskbase = mask + ((size_t)h * N_ + q0) * N_;

    for (int k0 = 0; k0 < N_; k0 += 64) {
        const float* Kg = g_K + ((size_t)h * N_ + k0) * HD_;
        const float* Vg = g_V + ((size_t)h * N_ + k0) * HD_;
        __syncthreads();   // all warps done with previous Ks/Vs (also orders first Q load)
        for (int i = threadIdx.x; i < 64 * 64; i += 256) {
            int r = i >> 6, d = i & 63;
            Ks[r * 65 + d] = Kg[i];
            Vs[i]          = Vg[i];
        }
        __syncthreads();

        // S = Q K^T for this warp's 8 rows; keys = lane, lane+32
        float s0[8], s1[8];
#pragma unroll
        for (int r = 0; r < 8; r++) { s0[r] = 0.f; s1[r] = 0.f; }
#pragma unroll 8
        for (int k = 0; k < 64; k++) {
            float kv0 = Ks[lane * 65 + k];
            float kv1 = Ks[(lane + 32) * 65 + k];
#pragma unroll
            for (int r = 0; r < 8; r++) {
                float q = Qs[(warp * 8 + r) * 64 + k];
                s0[r] += q * kv0;
                s1[r] += q * kv1;
            }
        }

        // Mask + online softmax (per row; warp-wide reductions)
#pragma unroll
        for (int r = 0; r < 8; r++) {
            const int* mr = maskbase + (size_t)(warp * 8 + r) * N_ + k0;
            float v0 = (mr[lane]      != 0) ? s0[r] * 0.125f : -1e30f;
            float v1 = (mr[lane + 32] != 0) ? s1[r] * 0.125f : -1e30f;
            float mx = fmaxf(v0, v1);
#pragma unroll
            for (int off = 16; off > 0; off >>= 1)
                mx = fmaxf(mx, __shfl_xor_sync(0xffffffffu, mx, off));
            float mnew = fmaxf(mrow[r], mx);
            float p0 = __expf(v0 - mnew);
            float p1 = __expf(v1 - mnew);
            float ps = p0 + p1;
#pragma unroll
            for (int off = 16; off > 0; off >>= 1)
                ps += __shfl_xor_sync(0xffffffffu, ps, off);
            float corr = __expf(mrow[r] - mnew);
            lrow[r] = lrow[r] * corr + ps;
            mrow[r] = mnew;
            O0[r] *= corr;
            O1[r] *= corr;
            Pw[r * 64 + lane]      = p0;
            Pw[r * 64 + lane + 32] = p1;
        }
        __syncwarp();

        // O += P V   (lane owns dims lane, lane+32 for all 8 rows)
#pragma unroll 8
        for (int k = 0; k < 64; k++) {
            float v0 = Vs[k * 64 + lane];
            float v1 = Vs[k * 64 + lane + 32];
#pragma unroll
            for (int r = 0; r < 8; r++) {
                float p = Pw[r * 64 + k];
                O0[r] += p * v0;
                O1[r] += p * v1;
            }
        }
    }

    // Epilogue: normalize and write into concat layout
#pragma unroll
    for (int r = 0; r < 8; r++) {
        float inv = 1.f / lrow[r];
        size_t row = (size_t)(q0 + warp * 8 + r);
        g_Hcat[row * (H_ * HD_) + h * HD_ + lane]      = O0[r] * inv;
        g_Hcat[row * (H_ * HD_) + h * HD_ + lane + 32] = O1[r] * inv;
    }
}

// ---------------------------------------------------------------------------
// Kernel 3: output projection.  out[n][c] = sum_k Hcat[n][k] * WO[c][k]
// ---------------------------------------------------------------------------
__global__ void oproj_kernel(const float* __restrict__ WO, float* __restrict__ out) {
    const int n0 = blockIdx.x * 64;
    const int c0 = blockIdx.y * 64;

    __shared__ float As[64][17];
    __shared__ float Bs[64][17];

    const int tx = threadIdx.x & 15;
    const int ty = threadIdx.x >> 4;
    const int lr = threadIdx.x >> 2;
    const int lc = (threadIdx.x & 3) << 2;

    float acc[4][4];
#pragma unroll
    for (int i = 0; i < 4; i++)
#pragma unroll
        for (int j = 0; j < 4; j++) acc[i][j] = 0.f;

    const int K = H_ * HD_;  // 512
    for (int k0 = 0; k0 < K; k0 += 16) {
        float4 av = *(const float4*)(g_Hcat + (size_t)(n0 + lr) * K + k0 + lc);
        float4 bv = *(const float4*)(WO + (size_t)(c0 + lr) * K + k0 + lc);
        As[lr][lc] = av.x; As[lr][lc + 1] = av.y; As[lr][lc + 2] = av.z; As[lr][lc + 3] = av.w;
        Bs[lr][lc] = bv.x; Bs[lr][lc + 1] = bv.y; Bs[lr][lc + 2] = bv.z; Bs[lr][lc + 3] = bv.w;
        __syncthreads();
#pragma unroll
        for (int kk = 0; kk < 16; kk++) {
            float a[4], b[4];
#pragma unroll
            for (int i = 0; i < 4; i++) a[i] = As[ty * 4 + i][kk];
#pragma unroll
            for (int j = 0; j < 4; j++) b[j] = Bs[tx * 4 + j][kk];
#pragma unroll
            for (int i = 0; i < 4; i++)
#pragma unroll
                for (int j = 0; j < 4; j++) acc[i][j] += a[i] * b[j];
        }
        __syncthreads();
    }

#pragma unroll
    for (int i = 0; i < 4; i++)
#pragma unroll
        for (int j = 0; j < 4; j++)
            out[(size_t)(n0 + ty * 4 + i) * FOUT_ + c0 + tx * 4 + j] = acc[i][j];
}

// ---------------------------------------------------------------------------
extern "C" void kernel_launch(void* const* d_in, const int* in_sizes, int n_in,
                              void* d_out, int out_size) {
    const float* X    = (const float*)d_in[0];
    const int*   mask = (const int*)d_in[1];
    const float* WQ   = (const float*)d_in[2];
    const float* WK   = (const float*)d_in[3];
    const float* WV   = (const float*)d_in[4];
    const float* WO   = (const float*)d_in[5];
    float*       out  = (float*)d_out;

    // 1) QKV projections
    qkv_kernel<<<dim3(N_ / 64, 3, H_), 256>>>(X, WQ, WK, WV);

    // 2) Flash attention (dynamic smem > 48KB -> opt in every call; capture-safe)
    size_t smem = (size_t)(64 * 64 + 64 * 65 + 64 * 64 + 8 * 8 * 64) * sizeof(float);
    cudaFuncSetAttribute(attn_kernel, cudaFuncAttributeMaxDynamicSharedMemorySize, (int)smem);
    attn_kernel<<<dim3(N_ / 64, H_), 256, smem>>>(mask);

    // 3) Output projection
    oproj_kernel<<<dim3(N_ / 64, FOUT_ / 64), 256>>>(WO, out);
}

// round 2
// speedup vs baseline: 1.3853x; 1.3853x over previous
#include <cuda_runtime.h>

#define H_    8
#define N_    4096
#define FIN_  512
#define HD_   64
#define FOUT_ 512

// Scratch (no cudaMalloc allowed)
__device__ float g_Q[H_ * N_ * HD_];
__device__ float g_K[H_ * N_ * HD_];
__device__ float g_V[H_ * N_ * HD_];
__device__ float g_Hcat[N_ * H_ * HD_];

// ---------------------------------------------------------------------------
// tf32 helpers
// ---------------------------------------------------------------------------
__device__ __forceinline__ unsigned f2tf(float x) {
    unsigned u;
    asm("cvt.rna.tf32.f32 %0, %1;" : "=r"(u) : "f"(x));
    return u;
}

// D = A(16x8) * B(8x8) + D,  A row-major, B col-major, f32 accum
__device__ __forceinline__ void mma8(float* c, unsigned a0, unsigned a1,
                                     unsigned a2, unsigned a3,
                                     unsigned b0, unsigned b1) {
    asm volatile(
        "mma.sync.aligned.m16n8k8.row.col.f32.tf32.tf32.f32 "
        "{%0,%1,%2,%3},{%4,%5,%6,%7},{%8,%9},{%0,%1,%2,%3};"
        : "+f"(c[0]), "+f"(c[1]), "+f"(c[2]), "+f"(c[3])
        : "r"(a0), "r"(a1), "r"(a2), "r"(a3), "r"(b0), "r"(b1));
}

// ---------------------------------------------------------------------------
// Generic NT GEMM tile: C[128][64] += A[128][K] * B[64][K]^T
// 256 threads = 8 warps, warp w owns rows 16w..16w+15, all 64 cols.
// ---------------------------------------------------------------------------
__device__ __forceinline__ void gemm_tile_128x64(
    const float* __restrict__ A, int lda,
    const float* __restrict__ B, int ldb,
    float* __restrict__ C, int ldc, int K)
{
    __shared__ unsigned As[128][36];   // pad 36 -> conflict-free frag reads
    __shared__ unsigned Bs[64][36];

    const int tid = threadIdx.x;
    const int warp = tid >> 5, lane = tid & 31;
    const int gr = lane >> 2, tc = lane & 3;

    float acc[8][4];
#pragma unroll
    for (int f = 0; f < 8; f++)
#pragma unroll
        for (int j = 0; j < 4; j++) acc[f][j] = 0.f;

    for (int k0 = 0; k0 < K; k0 += 32) {
        __syncthreads();
        // A chunk: 128x32 = 1024 float4
        for (int i = tid; i < 1024; i += 256) {
            int r = i >> 3, c = (i & 7) << 2;
            float4 v = *(const float4*)(A + (size_t)r * lda + k0 + c);
            As[r][c] = f2tf(v.x); As[r][c + 1] = f2tf(v.y);
            As[r][c + 2] = f2tf(v.z); As[r][c + 3] = f2tf(v.w);
        }
        // B chunk: 64x32 = 512 float4
        for (int i = tid; i < 512; i += 256) {
            int r = i >> 3, c = (i & 7) << 2;
            float4 v = *(const float4*)(B + (size_t)r * ldb + k0 + c);
            Bs[r][c] = f2tf(v.x); Bs[r][c + 1] = f2tf(v.y);
            Bs[r][c + 2] = f2tf(v.z); Bs[r][c + 3] = f2tf(v.w);
        }
        __syncthreads();

#pragma unroll
        for (int s = 0; s < 4; s++) {
            unsigned a0 = As[warp * 16 + gr][8 * s + tc];
            unsigned a1 = As[warp * 16 + gr + 8][8 * s + tc];
            unsigned a2 = As[warp * 16 + gr][8 * s + tc + 4];
            unsigned a3 = As[warp * 16 + gr + 8][8 * s + tc + 4];
#pragma unroll
            for (int f = 0; f < 8; f++) {
                unsigned b0 = Bs[8 * f + gr][8 * s + tc];
                unsigned b1 = Bs[8 * f + gr][8 * s + tc + 4];
                mma8(acc[f], a0, a1, a2, a3, b0, b1);
            }
        }
    }

#pragma unroll
    for (int f = 0; f < 8; f++) {
        int col = 8 * f + 2 * tc;
        float2 lo = make_float2(acc[f][0], acc[f][1]);
        float2 hi = make_float2(acc[f][2], acc[f][3]);
        *(float2*)(C + (size_t)(warp * 16 + gr) * ldc + col) = lo;
        *(float2*)(C + (size_t)(warp * 16 + gr + 8) * ldc + col) = hi;
    }
}

// ---------------------------------------------------------------------------
// Kernel 1: QKV projections.  grid = (N/128, 3, H)
// ---------------------------------------------------------------------------
__global__ void __launch_bounds__(256) qkv_mma(
    const float* __restrict__ X, const float* __restrict__ WQ,
    const float* __restrict__ WK, const float* __restrict__ WV)
{
    const int h = blockIdx.z, which = blockIdx.y;
    const float* W = (which == 0) ? WQ : (which == 1) ? WK : WV;
    float* Out = (which == 0) ? g_Q : (which == 1) ? g_K : g_V;
    const float* A = X + (size_t)h * N_ * FIN_ + (size_t)blockIdx.x * 128 * FIN_;
    gemm_tile_128x64(A, FIN_, W + (size_t)h * HD_ * FIN_, FIN_,
                     Out + (size_t)h * N_ * HD_ + (size_t)blockIdx.x * 128 * HD_,
                     HD_, FIN_);
}

// ---------------------------------------------------------------------------
// Kernel 3: O projection.  grid = (N/128, FOUT/64)
// ---------------------------------------------------------------------------
__global__ void __launch_bounds__(256) oproj_mma(
    const float* __restrict__ WO, float* __restrict__ out)
{
    const int K = H_ * HD_;
    gemm_tile_128x64(g_Hcat + (size_t)blockIdx.x * 128 * K, K,
                     WO + (size_t)blockIdx.y * 64 * K, K,
                     out + (size_t)blockIdx.x * 128 * FOUT_ + blockIdx.y * 64,
                     FOUT_, K);
}

// ---------------------------------------------------------------------------
// Kernel 2: flash attention, tf32 mma.
// Block: 256 thr (8 warps) -> 128 query rows; k-tiles of 64. grid (N/128, H)
// Warp w: rows 16w..16w+15. Q frags in registers for whole kernel.
// ---------------------------------------------------------------------------
__global__ void __launch_bounds__(256) attn_mma(const int* __restrict__ mask)
{
    const int h = blockIdx.y, q0 = blockIdx.x * 128;
    const int tid = threadIdx.x, warp = tid >> 5, lane = tid & 31;
    const int gr = lane >> 2, tc = lane & 3;

    __shared__ unsigned Ks[64][68];   // pad 68: conflict-free S-frag reads
    __shared__ unsigned Vs[64][72];   // pad 72: conflict-free PV column reads

    // Q fragments (row block q0+16*warp), kept in registers all kernel
    unsigned qa[8][4];
    {
        const float* Qg = g_Q + ((size_t)h * N_ + q0 + warp * 16) * HD_;
#pragma unroll
        for (int s = 0; s < 8; s++) {
            qa[s][0] = f2tf(Qg[(size_t)gr * 64 + 8 * s + tc]);
            qa[s][1] = f2tf(Qg[(size_t)(gr + 8) * 64 + 8 * s + tc]);
            qa[s][2] = f2tf(Qg[(size_t)gr * 64 + 8 * s + tc + 4]);
            qa[s][3] = f2tf(Qg[(size_t)(gr + 8) * 64 + 8 * s + tc + 4]);
        }
    }

    float O[8][4];
#pragma unroll
    for (int f = 0; f < 8; f++)
#pragma unroll
        for (int j = 0; j < 4; j++) O[f][j] = 0.f;
    float m_lo = -1e30f, m_hi = -1e30f, l_lo = 0.f, l_hi = 0.f;

    const int* mrow_lo = mask + ((size_t)h * N_ + q0 + warp * 16 + gr) * N_;
    const int* mrow_hi = mrow_lo + (size_t)8 * N_;

    for (int k0 = 0; k0 < N_; k0 += 64) {
        // ---- mask prefetch, packed to 2x16 bits to limit live registers ----
        unsigned mb_lo = 0, mb_hi = 0;
#pragma unroll
        for (int f = 0; f < 8; f++) {
            int2 a = *(const int2*)(mrow_lo + k0 + 8 * f + 2 * tc);
            int2 b = *(const int2*)(mrow_hi + k0 + 8 * f + 2 * tc);
            mb_lo |= (a.x != 0 ? 1u : 0u) << (2 * f);
            mb_lo |= (a.y != 0 ? 1u : 0u) << (2 * f + 1);
            mb_hi |= (b.x != 0 ? 1u : 0u) << (2 * f);
            mb_hi |= (b.y != 0 ? 1u : 0u) << (2 * f + 1);
        }

        __syncthreads();   // previous tile's K/V reads complete
        {
            const float* Kg = g_K + ((size_t)h * N_ + k0) * HD_;
            const float* Vg = g_V + ((size_t)h * N_ + k0) * HD_;
            for (int i = tid; i < 1024; i += 256) {   // 64x64/4
                int r = i >> 4, c = (i & 15) << 2;
                float4 kv = *(const float4*)(Kg + (size_t)r * 64 + c);
                float4 vv = *(const float4*)(Vg + (size_t)r * 64 + c);
                Ks[r][c] = f2tf(kv.x); Ks[r][c + 1] = f2tf(kv.y);
                Ks[r][c + 2] = f2tf(kv.z); Ks[r][c + 3] = f2tf(kv.w);
                Vs[r][c] = f2tf(vv.x); Vs[r][c + 1] = f2tf(vv.y);
                Vs[r][c + 2] = f2tf(vv.z); Vs[r][c + 3] = f2tf(vv.w);
            }
        }
        __syncthreads();

        // ---- S = Q K^T (per warp: 16 x 64) ----
        float S[8][4];
#pragma unroll
        for (int f = 0; f < 8; f++)
#pragma unroll
            for (int j = 0; j < 4; j++) S[f][j] = 0.f;
#pragma unroll
        for (int s = 0; s < 8; s++) {
#pragma unroll
            for (int f = 0; f < 8; f++) {
                unsigned b0 = Ks[8 * f + gr][8 * s + tc];
                unsigned b1 = Ks[8 * f + gr][8 * s + tc + 4];
                mma8(S[f], qa[s][0], qa[s][1], qa[s][2], qa[s][3], b0, b1);
            }
        }

        // ---- mask + scale ----
#pragma unroll
        for (int f = 0; f < 8; f++) {
            S[f][0] = (mb_lo >> (2 * f)) & 1 ? S[f][0] * 0.125f : -1e30f;
            S[f][1] = (mb_lo >> (2 * f + 1)) & 1 ? S[f][1] * 0.125f : -1e30f;
            S[f][2] = (mb_hi >> (2 * f)) & 1 ? S[f][2] * 0.125f : -1e30f;
            S[f][3] = (mb_hi >> (2 * f + 1)) & 1 ? S[f][3] * 0.125f : -1e30f;
        }

        // ---- online softmax (rows gr and gr+8) ----
        float mx_lo = -1e30f, mx_hi = -1e30f;
#pragma unroll
        for (int f = 0; f < 8; f++) {
            mx_lo = fmaxf(mx_lo, fmaxf(S[f][0], S[f][1]));
            mx_hi = fmaxf(mx_hi, fmaxf(S[f][2], S[f][3]));
        }
#pragma unroll
        for (int off = 1; off <= 2; off <<= 1) {
            mx_lo = fmaxf(mx_lo, __shfl_xor_sync(0xffffffffu, mx_lo, off));
            mx_hi = fmaxf(mx_hi, __shfl_xor_sync(0xffffffffu, mx_hi, off));
        }
        float mn_lo = fmaxf(m_lo, mx_lo), mn_hi = fmaxf(m_hi, mx_hi);
        float corr_lo = __expf(m_lo - mn_lo), corr_hi = __expf(m_hi - mn_hi);
        m_lo = mn_lo; m_hi = mn_hi;

        float ps_lo = 0.f, ps_hi = 0.f;
#pragma unroll
        for (int f = 0; f < 8; f++) {
            S[f][0] = __expf(S[f][0] - mn_lo);
            S[f][1] = __expf(S[f][1] - mn_lo);
            S[f][2] = __expf(S[f][2] - mn_hi);
            S[f][3] = __expf(S[f][3] - mn_hi);
            ps_lo += S[f][0] + S[f][1];
            ps_hi += S[f][2] + S[f][3];
        }
#pragma unroll
        for (int off = 1; off <= 2; off <<= 1) {
            ps_lo += __shfl_xor_sync(0xffffffffu, ps_lo, off);
            ps_hi += __shfl_xor_sync(0xffffffffu, ps_hi, off);
        }
        l_lo = l_lo * corr_lo + ps_lo;
        l_hi = l_hi * corr_hi + ps_hi;
#pragma unroll
        for (int f = 0; f < 8; f++) {
            O[f][0] *= corr_lo; O[f][1] *= corr_lo;
            O[f][2] *= corr_hi; O[f][3] *= corr_hi;
        }

        // ---- PV: shfl-transpose P (C-layout -> A-layout), then mma ----
        const int src0 = (lane & ~3) | (tc >> 1);
        const int src2 = src0 + 2;
        const bool oddc = tc & 1;
#pragma unroll
        for (int f = 0; f < 8; f++) {
            float e00 = __shfl_sync(0xffffffffu, S[f][0], src0);
            float e01 = __shfl_sync(0xffffffffu, S[f][1], src0);
            float e20 = __shfl_sync(0xffffffffu, S[f][0], src2);
            float e21 = __shfl_sync(0xffffffffu, S[f][1], src2);
            float e10 = __shfl_sync(0xffffffffu, S[f][2], src0);
            float e11 = __shfl_sync(0xffffffffu, S[f][3], src0);
            float e30 = __shfl_sync(0xffffffffu, S[f][2], src2);
            float e31 = __shfl_sync(0xffffffffu, S[f][3], src2);
            unsigned a0 = f2tf(oddc ? e01 : e00);
            unsigned a2 = f2tf(oddc ? e21 : e20);
            unsigned a1 = f2tf(oddc ? e11 : e10);
            unsigned a3 = f2tf(oddc ? e31 : e30);
#pragma unroll
            for (int g = 0; g < 8; g++) {
                unsigned b0 = Vs[8 * f + tc][8 * g + gr];
                unsigned b1 = Vs[8 * f + tc + 4][8 * g + gr];
                mma8(O[g], a0, a1, a2, a3, b0, b1);
            }
        }
    }

    // ---- epilogue: normalize, write concat layout ----
    float il_lo = 1.f / l_lo, il_hi = 1.f / l_hi;
    float* out_lo = g_Hcat + (size_t)(q0 + warp * 16 + gr) * (H_ * HD_) + h * HD_;
    float* out_hi = out_lo + (size_t)8 * (H_ * HD_);
#pragma unroll
    for (int f = 0; f < 8; f++) {
        int col = 8 * f + 2 * tc;
        *(float2*)(out_lo + col) = make_float2(O[f][0] * il_lo, O[f][1] * il_lo);
        *(float2*)(out_hi + col) = make_float2(O[f][2] * il_hi, O[f][3] * il_hi);
    }
}

// ---------------------------------------------------------------------------
extern "C" void kernel_launch(void* const* d_in, const int* in_sizes, int n_in,
                              void* d_out, int out_size) {
    const float* X    = (const float*)d_in[0];
    const int*   mask = (const int*)d_in[1];
    const float* WQ   = (const float*)d_in[2];
    const float* WK   = (const float*)d_in[3];
    const float* WV   = (const float*)d_in[4];
    const float* WO   = (const float*)d_in[5];
    float*       out  = (float*)d_out;

    qkv_mma<<<dim3(N_ / 128, 3, H_), 256>>>(X, WQ, WK, WV);
    attn_mma<<<dim3(N_ / 128, H_), 256>>>(mask);
    oproj_mma<<<dim3(N_ / 128, FOUT_ / 64), 256>>>(WO, out);
}

// round 3
// speedup vs baseline: 2.5130x; 1.8141x over previous
#include <cuda_runtime.h>

#define H_    8
#define N_    4096
#define FIN_  512
#define HD_   64
#define FOUT_ 512

// Scratch (no cudaMalloc allowed). g_Q/g_K/g_V hold tf32-rounded values.
__device__ float g_Q[H_ * N_ * HD_];
__device__ float g_K[H_ * N_ * HD_];
__device__ float g_V[H_ * N_ * HD_];
__device__ float g_Hcat[N_ * H_ * HD_];

// ---------------------------------------------------------------------------
__device__ __forceinline__ unsigned f2tf(float x) {
    unsigned u;
    asm("cvt.rna.tf32.f32 %0, %1;" : "=r"(u) : "f"(x));
    return u;
}

__device__ __forceinline__ void mma8(float* c, unsigned a0, unsigned a1,
                                     unsigned a2, unsigned a3,
                                     unsigned b0, unsigned b1) {
    asm volatile(
        "mma.sync.aligned.m16n8k8.row.col.f32.tf32.tf32.f32 "
        "{%0,%1,%2,%3},{%4,%5,%6,%7},{%8,%9},{%0,%1,%2,%3};"
        : "+f"(c[0]), "+f"(c[1]), "+f"(c[2]), "+f"(c[3])
        : "r"(a0), "r"(a1), "r"(a2), "r"(a3), "r"(b0), "r"(b1));
}

__device__ __forceinline__ void cp16(unsigned saddr, const void* gptr) {
    asm volatile("cp.async.cg.shared.global [%0], [%1], 16;" ::
                 "r"(saddr), "l"(gptr));
}

// ---------------------------------------------------------------------------
// Pipelined NT GEMM tile: C[128][64] = A[128][K] * B[64][K]^T
// 256 threads = 8 warps; register-prefetch software pipeline over 32-k chunks.
// ---------------------------------------------------------------------------
template <bool ROUND_STORE>
__device__ __forceinline__ void gemm_tile_128x64(
    const float* __restrict__ A, int lda,
    const float* __restrict__ B, int ldb,
    float* __restrict__ C, int ldc, int K)
{
    __shared__ unsigned As[128][36];
    __shared__ unsigned Bs[64][36];

    const int tid = threadIdx.x;
    const int warp = tid >> 5, lane = tid & 31;
    const int gr = lane >> 2, tc = lane & 3;

    float acc[8][4];
#pragma unroll
    for (int f = 0; f < 8; f++)
#pragma unroll
        for (int j = 0; j < 4; j++) acc[f][j] = 0.f;

    // prefetch registers
    float4 pa[4], pb[2];
    const int ar[4] = { tid >> 3, (tid + 256) >> 3, (tid + 512) >> 3, (tid + 768) >> 3 };
    const int ac = (tid & 7) << 2;
    const int br[2] = { tid >> 3, (tid + 256) >> 3 };

#pragma unroll
    for (int i = 0; i < 4; i++)
        pa[i] = *(const float4*)(A + (size_t)ar[i] * lda + ac);
#pragma unroll
    for (int i = 0; i < 2; i++)
        pb[i] = *(const float4*)(B + (size_t)br[i] * ldb + ac);

    const int nk = K >> 5;
    for (int kc = 0; kc < nk; kc++) {
        __syncthreads();
#pragma unroll
        for (int i = 0; i < 4; i++) {
            As[ar[i]][ac]     = f2tf(pa[i].x);
            As[ar[i]][ac + 1] = f2tf(pa[i].y);
            As[ar[i]][ac + 2] = f2tf(pa[i].z);
            As[ar[i]][ac + 3] = f2tf(pa[i].w);
        }
#pragma unroll
        for (int i = 0; i < 2; i++) {
            Bs[br[i]][ac]     = f2tf(pb[i].x);
            Bs[br[i]][ac + 1] = f2tf(pb[i].y);
            Bs[br[i]][ac + 2] = f2tf(pb[i].z);
            Bs[br[i]][ac + 3] = f2tf(pb[i].w);
        }
        __syncthreads();

        if (kc + 1 < nk) {
            int k0 = (kc + 1) << 5;
#pragma unroll
            for (int i = 0; i < 4; i++)
                pa[i] = *(const float4*)(A + (size_t)ar[i] * lda + k0 + ac);
#pragma unroll
            for (int i = 0; i < 2; i++)
                pb[i] = *(const float4*)(B + (size_t)br[i] * ldb + k0 + ac);
        }

#pragma unroll
        for (int s = 0; s < 4; s++) {
            unsigned a0 = As[warp * 16 + gr][8 * s + tc];
            unsigned a1 = As[warp * 16 + gr + 8][8 * s + tc];
            unsigned a2 = As[warp * 16 + gr][8 * s + tc + 4];
            unsigned a3 = As[warp * 16 + gr + 8][8 * s + tc + 4];
#pragma unroll
            for (int f = 0; f < 8; f++) {
                unsigned b0 = Bs[8 * f + gr][8 * s + tc];
                unsigned b1 = Bs[8 * f + gr][8 * s + tc + 4];
                mma8(acc[f], a0, a1, a2, a3, b0, b1);
            }
        }
    }

#pragma unroll
    for (int f = 0; f < 8; f++) {
        int col = 8 * f + 2 * tc;
        float v00 = acc[f][0], v01 = acc[f][1], v10 = acc[f][2], v11 = acc[f][3];
        if (ROUND_STORE) {
            v00 = __uint_as_float(f2tf(v00)); v01 = __uint_as_float(f2tf(v01));
            v10 = __uint_as_float(f2tf(v10)); v11 = __uint_as_float(f2tf(v11));
        }
        *(float2*)(C + (size_t)(warp * 16 + gr) * ldc + col) = make_float2(v00, v01);
        *(float2*)(C + (size_t)(warp * 16 + gr + 8) * ldc + col) = make_float2(v10, v11);
    }
}

__global__ void __launch_bounds__(256) qkv_mma(
    const float* __restrict__ X, const float* __restrict__ WQ,
    const float* __restrict__ WK, const float* __restrict__ WV)
{
    const int h = blockIdx.z, which = blockIdx.y;
    const float* W = (which == 0) ? WQ : (which == 1) ? WK : WV;
    float* Out = (which == 0) ? g_Q : (which == 1) ? g_K : g_V;
    const float* A = X + (size_t)h * N_ * FIN_ + (size_t)blockIdx.x * 128 * FIN_;
    gemm_tile_128x64<true>(A, FIN_, W + (size_t)h * HD_ * FIN_, FIN_,
                           Out + (size_t)h * N_ * HD_ + (size_t)blockIdx.x * 128 * HD_,
                           HD_, FIN_);
}

__global__ void __launch_bounds__(256) oproj_mma(
    const float* __restrict__ WO, float* __restrict__ out)
{
    const int K = H_ * HD_;
    gemm_tile_128x64<false>(g_Hcat + (size_t)blockIdx.x * 128 * K, K,
                            WO + (size_t)blockIdx.y * 64 * K, K,
                            out + (size_t)blockIdx.x * 128 * FOUT_ + blockIdx.y * 64,
                            FOUT_, K);
}

// ---------------------------------------------------------------------------
// Flash attention: cp.async double-buffered K/V + mask register prefetch.
// Block 256 thr (8 warps) = 128 query rows; 64-key tiles; grid (N/128, H).
// ---------------------------------------------------------------------------
#define KSTR  68
#define VSTR  72
#define KWORDS (64 * KSTR)
#define BUFW   (KWORDS + 64 * VSTR)     // words per buffer
#define ATTN_SMEM (2 * BUFW * 4)        // 71680 bytes

__global__ void __launch_bounds__(256, 1) attn_mma(const int* __restrict__ mask)
{
    extern __shared__ unsigned sm_kv[];
    const int h = blockIdx.y, q0 = blockIdx.x * 128;
    const int tid = threadIdx.x, warp = tid >> 5, lane = tid & 31;
    const int gr = lane >> 2, tc = lane & 3;

    const unsigned sbase = (unsigned)__cvta_generic_to_shared(sm_kv);
    const float* Kh = g_K + (size_t)h * N_ * HD_;
    const float* Vh = g_V + (size_t)h * N_ * HD_;

    const int fr = tid >> 4;               // 0..15: rows this thread fills (x4)
    const int fc = (tid & 15) << 2;        // float col 0,4,...,60

    // ---- issue cp.async for tile 0 into buffer 0 ----
    {
        const float* Kg = Kh;  const float* Vg = Vh;
        unsigned kb = sbase, vb = sbase + KWORDS * 4;
#pragma unroll
        for (int i = 0; i < 4; i++) {
            int r = fr + i * 16;
            cp16(kb + (r * KSTR + fc) * 4, Kg + (size_t)r * 64 + fc);
            cp16(vb + (r * VSTR + fc) * 4, Vg + (size_t)r * 64 + fc);
        }
        asm volatile("cp.async.commit_group;" ::: "memory");
    }

    // ---- Q fragments (already tf32-rounded in gmem) ----
    unsigned qa[8][4];
    {
        const float* Qg = g_Q + ((size_t)h * N_ + q0 + warp * 16) * HD_;
#pragma unroll
        for (int s = 0; s < 8; s++) {
            qa[s][0] = __float_as_uint(Qg[(size_t)gr * 64 + 8 * s + tc]);
            qa[s][1] = __float_as_uint(Qg[(size_t)(gr + 8) * 64 + 8 * s + tc]);
            qa[s][2] = __float_as_uint(Qg[(size_t)gr * 64 + 8 * s + tc + 4]);
            qa[s][3] = __float_as_uint(Qg[(size_t)(gr + 8) * 64 + 8 * s + tc + 4]);
        }
    }

    float O[8][4];
#pragma unroll
    for (int f = 0; f < 8; f++)
#pragma unroll
        for (int j = 0; j < 4; j++) O[f][j] = 0.f;
    float m_lo = -1e30f, m_hi = -1e30f, l_lo = 0.f, l_hi = 0.f;

    const int* mrow_lo = mask + ((size_t)h * N_ + q0 + warp * 16 + gr) * N_;
    const int* mrow_hi = mrow_lo + (size_t)8 * N_;

    // ---- mask tile 0 -> packed bits ----
    unsigned mb_lo = 0, mb_hi = 0;
    int2 mA[8], mB[8];
#pragma unroll
    for (int f = 0; f < 8; f++) {
        mA[f] = *(const int2*)(mrow_lo + 8 * f + 2 * tc);
        mB[f] = *(const int2*)(mrow_hi + 8 * f + 2 * tc);
    }
#pragma unroll
    for (int f = 0; f < 8; f++) {
        mb_lo |= (mA[f].x != 0 ? 1u : 0u) << (2 * f);
        mb_lo |= (mA[f].y != 0 ? 1u : 0u) << (2 * f + 1);
        mb_hi |= (mB[f].x != 0 ? 1u : 0u) << (2 * f);
        mb_hi |= (mB[f].y != 0 ? 1u : 0u) << (2 * f + 1);
    }

    const int NT = N_ / 64;
    for (int t = 0; t < NT; t++) {
        const int buf = t & 1;

        // ---- prefetch tile t+1: cp.async K/V + mask LDGs ----
        if (t + 1 < NT) {
            const int k1 = (t + 1) * 64;
            const float* Kg = Kh + (size_t)k1 * 64;
            const float* Vg = Vh + (size_t)k1 * 64;
            unsigned kb = sbase + ((buf ^ 1) * BUFW) * 4;
            unsigned vb = kb + KWORDS * 4;
#pragma unroll
            for (int i = 0; i < 4; i++) {
                int r = fr + i * 16;
                cp16(kb + (r * KSTR + fc) * 4, Kg + (size_t)r * 64 + fc);
                cp16(vb + (r * VSTR + fc) * 4, Vg + (size_t)r * 64 + fc);
            }
            asm volatile("cp.async.commit_group;" ::: "memory");
#pragma unroll
            for (int f = 0; f < 8; f++) {
                mA[f] = *(const int2*)(mrow_lo + k1 + 8 * f + 2 * tc);
                mB[f] = *(const int2*)(mrow_hi + k1 + 8 * f + 2 * tc);
            }
            asm volatile("cp.async.wait_group 1;" ::: "memory");
        } else {
            asm volatile("cp.async.wait_group 0;" ::: "memory");
        }
        __syncthreads();

        const unsigned* Ksb = sm_kv + buf * BUFW;
        const unsigned* Vsb = Ksb + KWORDS;

        // ---- S = Q K^T ----
        float S[8][4];
#pragma unroll
        for (int f = 0; f < 8; f++)
#pragma unroll
            for (int j = 0; j < 4; j++) S[f][j] = 0.f;
#pragma unroll
        for (int s = 0; s < 8; s++) {
#pragma unroll
            for (int f = 0; f < 8; f++) {
                unsigned b0 = Ksb[(8 * f + gr) * KSTR + 8 * s + tc];
                unsigned b1 = Ksb[(8 * f + gr) * KSTR + 8 * s + tc + 4];
                mma8(S[f], qa[s][0], qa[s][1], qa[s][2], qa[s][3], b0, b1);
            }
        }

        // ---- mask + scale ----
#pragma unroll
        for (int f = 0; f < 8; f++) {
            S[f][0] = (mb_lo >> (2 * f)) & 1 ? S[f][0] * 0.125f : -1e30f;
            S[f][1] = (mb_lo >> (2 * f + 1)) & 1 ? S[f][1] * 0.125f : -1e30f;
            S[f][2] = (mb_hi >> (2 * f)) & 1 ? S[f][2] * 0.125f : -1e30f;
            S[f][3] = (mb_hi >> (2 * f + 1)) & 1 ? S[f][3] * 0.125f : -1e30f;
        }

        // ---- online softmax ----
        float mx_lo = -1e30f, mx_hi = -1e30f;
#pragma unroll
        for (int f = 0; f < 8; f++) {
            mx_lo = fmaxf(mx_lo, fmaxf(S[f][0], S[f][1]));
            mx_hi = fmaxf(mx_hi, fmaxf(S[f][2], S[f][3]));
        }
#pragma unroll
        for (int off = 1; off <= 2; off <<= 1) {
            mx_lo = fmaxf(mx_lo, __shfl_xor_sync(0xffffffffu, mx_lo, off));
            mx_hi = fmaxf(mx_hi, __shfl_xor_sync(0xffffffffu, mx_hi, off));
        }
        float mn_lo = fmaxf(m_lo, mx_lo), mn_hi = fmaxf(m_hi, mx_hi);
        float corr_lo = __expf(m_lo - mn_lo), corr_hi = __expf(m_hi - mn_hi);
        m_lo = mn_lo; m_hi = mn_hi;

        float ps_lo = 0.f, ps_hi = 0.f;
#pragma unroll
        for (int f = 0; f < 8; f++) {
            S[f][0] = __expf(S[f][0] - mn_lo);
            S[f][1] = __expf(S[f][1] - mn_lo);
            S[f][2] = __expf(S[f][2] - mn_hi);
            S[f][3] = __expf(S[f][3] - mn_hi);
            ps_lo += S[f][0] + S[f][1];
            ps_hi += S[f][2] + S[f][3];
        }
#pragma unroll
        for (int off = 1; off <= 2; off <<= 1) {
            ps_lo += __shfl_xor_sync(0xffffffffu, ps_lo, off);
            ps_hi += __shfl_xor_sync(0xffffffffu, ps_hi, off);
        }
        l_lo = l_lo * corr_lo + ps_lo;
        l_hi = l_hi * corr_hi + ps_hi;
#pragma unroll
        for (int f = 0; f < 8; f++) {
            O[f][0] *= corr_lo; O[f][1] *= corr_lo;
            O[f][2] *= corr_hi; O[f][3] *= corr_hi;
        }

        // ---- PV with in-register shfl transpose ----
        const int src0 = (lane & ~3) | (tc >> 1);
        const int src2 = src0 + 2;
        const bool oddc = tc & 1;
#pragma unroll
        for (int f = 0; f < 8; f++) {
            float e00 = __shfl_sync(0xffffffffu, S[f][0], src0);
            float e01 = __shfl_sync(0xffffffffu, S[f][1], src0);
            float e20 = __shfl_sync(0xffffffffu, S[f][0], src2);
            float e21 = __shfl_sync(0xffffffffu, S[f][1], src2);
            float e10 = __shfl_sync(0xffffffffu, S[f][2], src0);
            float e11 = __shfl_sync(0xffffffffu, S[f][3], src0);
            float e30 = __shfl_sync(0xffffffffu, S[f][2], src2);
            float e31 = __shfl_sync(0xffffffffu, S[f][3], src2);
            unsigned a0 = f2tf(oddc ? e01 : e00);
            unsigned a2 = f2tf(oddc ? e21 : e20);
            unsigned a1 = f2tf(oddc ? e11 : e10);
            unsigned a3 = f2tf(oddc ? e31 : e30);
#pragma unroll
            for (int g = 0; g < 8; g++) {
                unsigned b0 = Vsb[(8 * f + tc) * VSTR + 8 * g + gr];
                unsigned b1 = Vsb[(8 * f + tc + 4) * VSTR + 8 * g + gr];
                mma8(O[g], a0, a1, a2, a3, b0, b1);
            }
        }

        // ---- pack next tile's mask bits ----
        if (t + 1 < NT) {
            mb_lo = 0; mb_hi = 0;
#pragma unroll
            for (int f = 0; f < 8; f++) {
                mb_lo |= (mA[f].x != 0 ? 1u : 0u) << (2 * f);
                mb_lo |= (mA[f].y != 0 ? 1u : 0u) << (2 * f + 1);
                mb_hi |= (mB[f].x != 0 ? 1u : 0u) << (2 * f);
                mb_hi |= (mB[f].y != 0 ? 1u : 0u) << (2 * f + 1);
            }
        }
        __syncthreads();   // all warps done reading buf before it is refilled
    }

    // ---- epilogue ----
    float il_lo = 1.f / l_lo, il_hi = 1.f / l_hi;
    float* out_lo = g_Hcat + (size_t)(q0 + warp * 16 + gr) * (H_ * HD_) + h * HD_;
    float* out_hi = out_lo + (size_t)8 * (H_ * HD_);
#pragma unroll
    for (int f = 0; f < 8; f++) {
        int col = 8 * f + 2 * tc;
        *(float2*)(out_lo + col) = make_float2(O[f][0] * il_lo, O[f][1] * il_lo);
        *(float2*)(out_hi + col) = make_float2(O[f][2] * il_hi, O[f][3] * il_hi);
    }
}

// ---------------------------------------------------------------------------
extern "C" void kernel_launch(void* const* d_in, const int* in_sizes, int n_in,
                              void* d_out, int out_size) {
    const float* X    = (const float*)d_in[0];
    const int*   mask = (const int*)d_in[1];
    const float* WQ   = (const float*)d_in[2];
    const float* WK   = (const float*)d_in[3];
    const float* WV   = (const float*)d_in[4];
    const float* WO   = (const float*)d_in[5];
    float*       out  = (float*)d_out;

    qkv_mma<<<dim3(N_ / 128, 3, H_), 256>>>(X, WQ, WK, WV);

    cudaFuncSetAttribute(attn_mma, cudaFuncAttributeMaxDynamicSharedMemorySize,
                         ATTN_SMEM);
    attn_mma<<<dim3(N_ / 128, H_), 256, ATTN_SMEM>>>(mask);

    oproj_mma<<<dim3(N_ / 128, FOUT_ / 64), 256>>>(WO, out);
}

// round 6
// speedup vs baseline: 3.3311x; 1.3255x over previous
#include <cuda_runtime.h>

#define H_    8
#define N_    4096
#define FIN_  512
#define HD_   64
#define FOUT_ 512
#define NW_   (N_ / 32)   // 128 mask words per row

// Scratch (no cudaMalloc allowed). g_Q/g_K/g_V hold tf32-rounded values.
__device__ float g_Q[H_ * N_ * HD_];
__device__ float g_K[H_ * N_ * HD_];
__device__ float g_V[H_ * N_ * HD_];
__device__ float g_Hcat[N_ * H_ * HD_];
__device__ __align__(16) unsigned g_maskbits[H_ * N_ * NW_];   // 16.8MB bitmask

// ---------------------------------------------------------------------------
__device__ __forceinline__ unsigned f2tf(float x) {
    unsigned u;
    asm("cvt.rna.tf32.f32 %0, %1;" : "=r"(u) : "f"(x));
    return u;
}

__device__ __forceinline__ void mma8(float* c, unsigned a0, unsigned a1,
                                     unsigned a2, unsigned a3,
                                     unsigned b0, unsigned b1) {
    asm volatile(
        "mma.sync.aligned.m16n8k8.row.col.f32.tf32.tf32.f32 "
        "{%0,%1,%2,%3},{%4,%5,%6,%7},{%8,%9},{%0,%1,%2,%3};"
        : "+f"(c[0]), "+f"(c[1]), "+f"(c[2]), "+f"(c[3])
        : "r"(a0), "r"(a1), "r"(a2), "r"(a3), "r"(b0), "r"(b1));
}

__device__ __forceinline__ void cp16(unsigned saddr, const void* gptr) {
    asm volatile("cp.async.cg.shared.global [%0], [%1], 16;" ::
                 "r"(saddr), "l"(gptr));
}

// ---------------------------------------------------------------------------
// Kernel 0: pack mask int32 -> bits.  1 warp packs 1 row (4096 cols).
// grid = H*N/8 blocks of 256.  Coalesced 128B reads, MLP=32.
// ---------------------------------------------------------------------------
__global__ void __launch_bounds__(256) maskpack(const int* __restrict__ mask)
{
    const int row  = blockIdx.x * 8 + (threadIdx.x >> 5);
    const int lane = threadIdx.x & 31;
    const int* mrow = mask + (size_t)row * N_;
    unsigned* orow  = g_maskbits + (size_t)row * NW_;

    for (int c0 = 0; c0 < N_; c0 += 1024) {
        int v[32];
#pragma unroll
        for (int j = 0; j < 32; j++) v[j] = mrow[c0 + j * 32 + lane];
        unsigned word = 0;
#pragma unroll
        for (int j = 0; j < 32; j++) {
            unsigned b = __ballot_sync(0xffffffffu, v[j] != 0);
            if (lane == j) word = b;
        }
        orow[(c0 >> 5) + lane] = word;
    }
}

// ---------------------------------------------------------------------------
// Pipelined NT GEMM tile: C[128][64] = A[128][K] * B[64][K]^T
// ---------------------------------------------------------------------------
template <bool ROUND_STORE>
__device__ __forceinline__ void gemm_tile_128x64(
    const float* __restrict__ A, int lda,
    const float* __restrict__ B, int ldb,
    float* __restrict__ C, int ldc, int K)
{
    __shared__ unsigned As[128][36];
    __shared__ unsigned Bs[64][36];

    const int tid = threadIdx.x;
    const int warp = tid >> 5, lane = tid & 31;
    const int gr = lane >> 2, tc = lane & 3;

    float acc[8][4];
#pragma unroll
    for (int f = 0; f < 8; f++)
#pragma unroll
        for (int j = 0; j < 4; j++) acc[f][j] = 0.f;

    float4 pa[4], pb[2];
    const int ar[4] = { tid >> 3, (tid + 256) >> 3, (tid + 512) >> 3, (tid + 768) >> 3 };
    const int ac = (tid & 7) << 2;
    const int br[2] = { tid >> 3, (tid + 256) >> 3 };

#pragma unroll
    for (int i = 0; i < 4; i++)
        pa[i] = *(const float4*)(A + (size_t)ar[i] * lda + ac);
#pragma unroll
    for (int i = 0; i < 2; i++)
        pb[i] = *(const float4*)(B + (size_t)br[i] * ldb + ac);

    const int nk = K >> 5;
    for (int kc = 0; kc < nk; kc++) {
        __syncthreads();
#pragma unroll
        for (int i = 0; i < 4; i++) {
            As[ar[i]][ac]     = f2tf(pa[i].x);
            As[ar[i]][ac + 1] = f2tf(pa[i].y);
            As[ar[i]][ac + 2] = f2tf(pa[i].z);
            As[ar[i]][ac + 3] = f2tf(pa[i].w);
        }
#pragma unroll
        for (int i = 0; i < 2; i++) {
            Bs[br[i]][ac]     = f2tf(pb[i].x);
            Bs[br[i]][ac + 1] = f2tf(pb[i].y);
            Bs[br[i]][ac + 2] = f2tf(pb[i].z);
            Bs[br[i]][ac + 3] = f2tf(pb[i].w);
        }
        __syncthreads();

        if (kc + 1 < nk) {
            int k0 = (kc + 1) << 5;
#pragma unroll
            for (int i = 0; i < 4; i++)
                pa[i] = *(const float4*)(A + (size_t)ar[i] * lda + k0 + ac);
#pragma unroll
            for (int i = 0; i < 2; i++)
                pb[i] = *(const float4*)(B + (size_t)br[i] * ldb + k0 + ac);
        }

#pragma unroll
        for (int s = 0; s < 4; s++) {
            unsigned a0 = As[warp * 16 + gr][8 * s + tc];
            unsigned a1 = As[warp * 16 + gr + 8][8 * s + tc];
            unsigned a2 = As[warp * 16 + gr][8 * s + tc + 4];
            unsigned a3 = As[warp * 16 + gr + 8][8 * s + tc + 4];
#pragma unroll
            for (int f = 0; f < 8; f++) {
                unsigned b0 = Bs[8 * f + gr][8 * s + tc];
                unsigned b1 = Bs[8 * f + gr][8 * s + tc + 4];
                mma8(acc[f], a0, a1, a2, a3, b0, b1);
            }
        }
    }

#pragma unroll
    for (int f = 0; f < 8; f++) {
        int col = 8 * f + 2 * tc;
        float v00 = acc[f][0], v01 = acc[f][1], v10 = acc[f][2], v11 = acc[f][3];
        if (ROUND_STORE) {
            v00 = __uint_as_float(f2tf(v00)); v01 = __uint_as_float(f2tf(v01));
            v10 = __uint_as_float(f2tf(v10)); v11 = __uint_as_float(f2tf(v11));
        }
        *(float2*)(C + (size_t)(warp * 16 + gr) * ldc + col) = make_float2(v00, v01);
        *(float2*)(C + (size_t)(warp * 16 + gr + 8) * ldc + col) = make_float2(v10, v11);
    }
}

__global__ void __launch_bounds__(256) qkv_mma(
    const float* __restrict__ X, const float* __restrict__ WQ,
    const float* __restrict__ WK, const float* __restrict__ WV)
{
    const int h = blockIdx.z, which = blockIdx.y;
    const float* W = (which == 0) ? WQ : (which == 1) ? WK : WV;
    float* Out = (which == 0) ? g_Q : (which == 1) ? g_K : g_V;
    const float* A = X + (size_t)h * N_ * FIN_ + (size_t)blockIdx.x * 128 * FIN_;
    gemm_tile_128x64<true>(A, FIN_, W + (size_t)h * HD_ * FIN_, FIN_,
                           Out + (size_t)h * N_ * HD_ + (size_t)blockIdx.x * 128 * HD_,
                           HD_, FIN_);
}

__global__ void __launch_bounds__(256) oproj_mma(
    const float* __restrict__ WO, float* __restrict__ out)
{
    const int K = H_ * HD_;
    gemm_tile_128x64<false>(g_Hcat + (size_t)blockIdx.x * 128 * K, K,
                            WO + (size_t)blockIdx.y * 64 * K, K,
                            out + (size_t)blockIdx.x * 128 * FOUT_ + blockIdx.y * 64,
                            FOUT_, K);
}

// ---------------------------------------------------------------------------
// Flash attention: cp.async double-buffer, packed mask bits, 2 CTAs/SM.
// ---------------------------------------------------------------------------
#define KSTR  68
#define VSTR  72
#define KWORDS (64 * KSTR)
#define BUFW   (KWORDS + 64 * VSTR)
#define ATTN_SMEM (2 * BUFW * 4)        // 71680 bytes -> 2 CTAs/SM

__global__ void __launch_bounds__(256, 2) attn_mma(void)
{
    extern __shared__ unsigned sm_kv[];
    const int h = blockIdx.y, q0 = blockIdx.x * 128;
    const int tid = threadIdx.x, warp = tid >> 5, lane = tid & 31;
    const int gr = lane >> 2, tc = lane & 3;

    const unsigned sbase = (unsigned)__cvta_generic_to_shared(sm_kv);
    const float* Kh = g_K + (size_t)h * N_ * HD_;
    const float* Vh = g_V + (size_t)h * N_ * HD_;

    const int fr = tid >> 4;
    const int fc = (tid & 15) << 2;

    // cp.async tile 0 -> buffer 0
    {
        unsigned kb = sbase, vb = sbase + KWORDS * 4;
#pragma unroll
        for (int i = 0; i < 4; i++) {
            int r = fr + i * 16;
            cp16(kb + (r * KSTR + fc) * 4, Kh + (size_t)r * 64 + fc);
            cp16(vb + (r * VSTR + fc) * 4, Vh + (size_t)r * 64 + fc);
        }
        asm volatile("cp.async.commit_group;" ::: "memory");
    }

    // Q fragments (tf32-rounded in gmem)
    unsigned qa[8][4];
    {
        const float* Qg = g_Q + ((size_t)h * N_ + q0 + warp * 16) * HD_;
#pragma unroll
        for (int s = 0; s < 8; s++) {
            qa[s][0] = __float_as_uint(Qg[(size_t)gr * 64 + 8 * s + tc]);
            qa[s][1] = __float_as_uint(Qg[(size_t)(gr + 8) * 64 + 8 * s + tc]);
            qa[s][2] = __float_as_uint(Qg[(size_t)gr * 64 + 8 * s + tc + 4]);
            qa[s][3] = __float_as_uint(Qg[(size_t)(gr + 8) * 64 + 8 * s + tc + 4]);
        }
    }

    float O[8][4];
#pragma unroll
    for (int f = 0; f < 8; f++)
#pragma unroll
        for (int j = 0; j < 4; j++) O[f][j] = 0.f;
    float m_lo = -1e30f, m_hi = -1e30f, l_lo = 0.f, l_hi = 0.f;

    // packed mask rows (2 words per 64-key tile, uint2 per row)
    const unsigned* Mrow_lo = g_maskbits + (size_t)(h * N_ + q0 + warp * 16 + gr) * NW_;
    const unsigned* Mrow_hi = Mrow_lo + (size_t)8 * NW_;
    uint2 wl = *(const uint2*)(Mrow_lo);
    uint2 wh = *(const uint2*)(Mrow_hi);

    const int NT = N_ / 64;
    for (int t = 0; t < NT; t++) {
        const int buf = t & 1;

        uint2 nwl, nwh;
        if (t + 1 < NT) {
            const int k1 = (t + 1) * 64;
            const float* Kg = Kh + (size_t)k1 * 64;
            const float* Vg = Vh + (size_t)k1 * 64;
            unsigned kb = sbase + ((buf ^ 1) * BUFW) * 4;
            unsigned vb = kb + KWORDS * 4;
#pragma unroll
            for (int i = 0; i < 4; i++) {
                int r = fr + i * 16;
                cp16(kb + (r * KSTR + fc) * 4, Kg + (size_t)r * 64 + fc);
                cp16(vb + (r * VSTR + fc) * 4, Vg + (size_t)r * 64 + fc);
            }
            asm volatile("cp.async.commit_group;" ::: "memory");
            nwl = *(const uint2*)(Mrow_lo + 2 * (t + 1));
            nwh = *(const uint2*)(Mrow_hi + 2 * (t + 1));
            asm volatile("cp.async.wait_group 1;" ::: "memory");
        } else {
            asm volatile("cp.async.wait_group 0;" ::: "memory");
        }
        __syncthreads();

        const unsigned* Ksb = sm_kv + buf * BUFW;
        const unsigned* Vsb = Ksb + KWORDS;

        // S = Q K^T
        float S[8][4];
#pragma unroll
        for (int f = 0; f < 8; f++)
#pragma unroll
            for (int j = 0; j < 4; j++) S[f][j] = 0.f;
#pragma unroll
        for (int s = 0; s < 8; s++) {
#pragma unroll
            for (int f = 0; f < 8; f++) {
                unsigned b0 = Ksb[(8 * f + gr) * KSTR + 8 * s + tc];
                unsigned b1 = Ksb[(8 * f + gr) * KSTR + 8 * s + tc + 4];
                mma8(S[f], qa[s][0], qa[s][1], qa[s][2], qa[s][3], b0, b1);
            }
        }

        // mask (from packed bits) + scale
        const int sh0 = 2 * tc;
#pragma unroll
        for (int f = 0; f < 8; f++) {
            unsigned w_lo = (f < 4) ? wl.x : wl.y;
            unsigned w_hi = (f < 4) ? wh.x : wh.y;
            int sh = ((8 * f) & 31) + sh0;
            S[f][0] = ((w_lo >> sh) & 1)       ? S[f][0] * 0.125f : -1e30f;
            S[f][1] = ((w_lo >> (sh + 1)) & 1) ? S[f][1] * 0.125f : -1e30f;
            S[f][2] = ((w_hi >> sh) & 1)       ? S[f][2] * 0.125f : -1e30f;
            S[f][3] = ((w_hi >> (sh + 1)) & 1) ? S[f][3] * 0.125f : -1e30f;
        }

        // online softmax
        float mx_lo = -1e30f, mx_hi = -1e30f;
#pragma unroll
        for (int f = 0; f < 8; f++) {
            mx_lo = fmaxf(mx_lo, fmaxf(S[f][0], S[f][1]));
            mx_hi = fmaxf(mx_hi, fmaxf(S[f][2], S[f][3]));
        }
#pragma unroll
        for (int off = 1; off <= 2; off <<= 1) {
            mx_lo = fmaxf(mx_lo, __shfl_xor_sync(0xffffffffu, mx_lo, off));
            mx_hi = fmaxf(mx_hi, __shfl_xor_sync(0xffffffffu, mx_hi, off));
        }
        float mn_lo = fmaxf(m_lo, mx_lo), mn_hi = fmaxf(m_hi, mx_hi);
        float corr_lo = __expf(m_lo - mn_lo), corr_hi = __expf(m_hi - mn_hi);
        m_lo = mn_lo; m_hi = mn_hi;

        float ps_lo = 0.f, ps_hi = 0.f;
#pragma unroll
        for (int f = 0; f < 8; f++) {
            S[f][0] = __expf(S[f][0] - mn_lo);
            S[f][1] = __expf(S[f][1] - mn_lo);
            S[f][2] = __expf(S[f][2] - mn_hi);
            S[f][3] = __expf(S[f][3] - mn_hi);
            ps_lo += S[f][0] + S[f][1];
            ps_hi += S[f][2] + S[f][3];
        }
#pragma unroll
        for (int off = 1; off <= 2; off <<= 1) {
            ps_lo += __shfl_xor_sync(0xffffffffu, ps_lo, off);
            ps_hi += __shfl_xor_sync(0xffffffffu, ps_hi, off);
        }
        l_lo = l_lo * corr_lo + ps_lo;
        l_hi = l_hi * corr_hi + ps_hi;
#pragma unroll
        for (int f = 0; f < 8; f++) {
            O[f][0] *= corr_lo; O[f][1] *= corr_lo;
            O[f][2] *= corr_hi; O[f][3] *= corr_hi;
        }

        // PV with in-register shfl transpose
        const int src0 = (lane & ~3) | (tc >> 1);
        const int src2 = src0 + 2;
        const bool oddc = tc & 1;
#pragma unroll
        for (int f = 0; f < 8; f++) {
            float e00 = __shfl_sync(0xffffffffu, S[f][0], src0);
            float e01 = __shfl_sync(0xffffffffu, S[f][1], src0);
            float e20 = __shfl_sync(0xffffffffu, S[f][0], src2);
            float e21 = __shfl_sync(0xffffffffu, S[f][1], src2);
            float e10 = __shfl_sync(0xffffffffu, S[f][2], src0);
            float e11 = __shfl_sync(0xffffffffu, S[f][3], src0);
            float e30 = __shfl_sync(0xffffffffu, S[f][2], src2);
            float e31 = __shfl_sync(0xffffffffu, S[f][3], src2);
            unsigned a0 = f2tf(oddc ? e01 : e00);
            unsigned a2 = f2tf(oddc ? e21 : e20);
            unsigned a1 = f2tf(oddc ? e11 : e10);
            unsigned a3 = f2tf(oddc ? e31 : e30);
#pragma unroll
            for (int g = 0; g < 8; g++) {
                unsigned b0 = Vsb[(8 * f + tc) * VSTR + 8 * g + gr];
                unsigned b1 = Vsb[(8 * f + tc + 4) * VSTR + 8 * g + gr];
                mma8(O[g], a0, a1, a2, a3, b0, b1);
            }
        }

        if (t + 1 < NT) { wl = nwl; wh = nwh; }
        __syncthreads();
    }

    // epilogue
    float il_lo = 1.f / l_lo, il_hi = 1.f / l_hi;
    float* out_lo = g_Hcat + (size_t)(q0 + warp * 16 + gr) * (H_ * HD_) + h * HD_;
    float* out_hi = out_lo + (size_t)8 * (H_ * HD_);
#pragma unroll
    for (int f = 0; f < 8; f++) {
        int col = 8 * f + 2 * tc;
        *(float2*)(out_lo + col) = make_float2(O[f][0] * il_lo, O[f][1] * il_lo);
        *(float2*)(out_hi + col) = make_float2(O[f][2] * il_hi, O[f][3] * il_hi);
    }
}

// ---------------------------------------------------------------------------
extern "C" void kernel_launch(void* const* d_in, const int* in_sizes, int n_in,
                              void* d_out, int out_size) {
    const float* X    = (const float*)d_in[0];
    const int*   mask = (const int*)d_in[1];
    const float* WQ   = (const float*)d_in[2];
    const float* WK   = (const float*)d_in[3];
    const float* WV   = (const float*)d_in[4];
    const float* WO   = (const float*)d_in[5];
    float*       out  = (float*)d_out;

    maskpack<<<H_ * N_ / 8, 256>>>(mask);
    qkv_mma<<<dim3(N_ / 128, 3, H_), 256>>>(X, WQ, WK, WV);

    cudaFuncSetAttribute(attn_mma, cudaFuncAttributeMaxDynamicSharedMemorySize,
                         ATTN_SMEM);
    attn_mma<<<dim3(N_ / 128, H_), 256, ATTN_SMEM>>>();

    oproj_mma<<<dim3(N_ / 128, FOUT_ / 64), 256>>>(WO, out);
}

// round 7
// speedup vs baseline: 3.5062x; 1.0526x over previous
#include <cuda_runtime.h>

#define H_    8
#define N_    4096
#define FIN_  512
#define HD_   64
#define FOUT_ 512
#define NW_   (N_ / 32)   // 128 mask words per row

// Scratch (no cudaMalloc allowed). g_Q/g_K/g_V hold tf32-rounded values.
__device__ float g_Q[H_ * N_ * HD_];
__device__ float g_K[H_ * N_ * HD_];
__device__ float g_V[H_ * N_ * HD_];
__device__ float g_Hcat[N_ * H_ * HD_];
__device__ __align__(16) unsigned g_maskbits[H_ * N_ * NW_];   // 16.8MB bitmask

// ---------------------------------------------------------------------------
__device__ __forceinline__ unsigned f2tf(float x) {
    unsigned u;
    asm("cvt.rna.tf32.f32 %0, %1;" : "=r"(u) : "f"(x));
    return u;
}

__device__ __forceinline__ void mma8(float* c, unsigned a0, unsigned a1,
                                     unsigned a2, unsigned a3,
                                     unsigned b0, unsigned b1) {
    asm volatile(
        "mma.sync.aligned.m16n8k8.row.col.f32.tf32.tf32.f32 "
        "{%0,%1,%2,%3},{%4,%5,%6,%7},{%8,%9},{%0,%1,%2,%3};"
        : "+f"(c[0]), "+f"(c[1]), "+f"(c[2]), "+f"(c[3])
        : "r"(a0), "r"(a1), "r"(a2), "r"(a3), "r"(b0), "r"(b1));
}

__device__ __forceinline__ void cp16(unsigned saddr, const void* gptr) {
    asm volatile("cp.async.cg.shared.global [%0], [%1], 16;" ::
                 "r"(saddr), "l"(gptr));
}

// ---------------------------------------------------------------------------
// Pipelined NT GEMM tile: C[128][64] = A[128][K] * B[64][K]^T
// ---------------------------------------------------------------------------
template <bool ROUND_STORE>
__device__ __forceinline__ void gemm_tile_128x64(
    const float* __restrict__ A, int lda,
    const float* __restrict__ B, int ldb,
    float* __restrict__ C, int ldc, int K)
{
    __shared__ unsigned As[128][36];
    __shared__ unsigned Bs[64][36];

    const int tid = threadIdx.x;
    const int warp = tid >> 5, lane = tid & 31;
    const int gr = lane >> 2, tc = lane & 3;

    float acc[8][4];
#pragma unroll
    for (int f = 0; f < 8; f++)
#pragma unroll
        for (int j = 0; j < 4; j++) acc[f][j] = 0.f;

    float4 pa[4], pb[2];
    const int ar[4] = { tid >> 3, (tid + 256) >> 3, (tid + 512) >> 3, (tid + 768) >> 3 };
    const int ac = (tid & 7) << 2;
    const int br[2] = { tid >> 3, (tid + 256) >> 3 };

#pragma unroll
    for (int i = 0; i < 4; i++)
        pa[i] = *(const float4*)(A + (size_t)ar[i] * lda + ac);
#pragma unroll
    for (int i = 0; i < 2; i++)
        pb[i] = *(const float4*)(B + (size_t)br[i] * ldb + ac);

    const int nk = K >> 5;
    for (int kc = 0; kc < nk; kc++) {
        __syncthreads();
#pragma unroll
        for (int i = 0; i < 4; i++) {
            As[ar[i]][ac]     = f2tf(pa[i].x);
            As[ar[i]][ac + 1] = f2tf(pa[i].y);
            As[ar[i]][ac + 2] = f2tf(pa[i].z);
            As[ar[i]][ac + 3] = f2tf(pa[i].w);
        }
#pragma unroll
        for (int i = 0; i < 2; i++) {
            Bs[br[i]][ac]     = f2tf(pb[i].x);
            Bs[br[i]][ac + 1] = f2tf(pb[i].y);
            Bs[br[i]][ac + 2] = f2tf(pb[i].z);
            Bs[br[i]][ac + 3] = f2tf(pb[i].w);
        }
        __syncthreads();

        if (kc + 1 < nk) {
            int k0 = (kc + 1) << 5;
#pragma unroll
            for (int i = 0; i < 4; i++)
                pa[i] = *(const float4*)(A + (size_t)ar[i] * lda + k0 + ac);
#pragma unroll
            for (int i = 0; i < 2; i++)
                pb[i] = *(const float4*)(B + (size_t)br[i] * ldb + k0 + ac);
        }

#pragma unroll
        for (int s = 0; s < 4; s++) {
            unsigned a0 = As[warp * 16 + gr][8 * s + tc];
            unsigned a1 = As[warp * 16 + gr + 8][8 * s + tc];
            unsigned a2 = As[warp * 16 + gr][8 * s + tc + 4];
            unsigned a3 = As[warp * 16 + gr + 8][8 * s + tc + 4];
#pragma unroll
            for (int f = 0; f < 8; f++) {
                unsigned b0 = Bs[8 * f + gr][8 * s + tc];
                unsigned b1 = Bs[8 * f + gr][8 * s + tc + 4];
                mma8(acc[f], a0, a1, a2, a3, b0, b1);
            }
        }
    }

#pragma unroll
    for (int f = 0; f < 8; f++) {
        int col = 8 * f + 2 * tc;
        float v00 = acc[f][0], v01 = acc[f][1], v10 = acc[f][2], v11 = acc[f][3];
        if (ROUND_STORE) {
            v00 = __uint_as_float(f2tf(v00)); v01 = __uint_as_float(f2tf(v01));
            v10 = __uint_as_float(f2tf(v10)); v11 = __uint_as_float(f2tf(v11));
        }
        *(float2*)(C + (size_t)(warp * 16 + gr) * ldc + col) = make_float2(v00, v01);
        *(float2*)(C + (size_t)(warp * 16 + gr + 8) * ldc + col) = make_float2(v10, v11);
    }
}

// ---------------------------------------------------------------------------
// Kernel 1 (fused): blocks [0,768) do QKV projection; blocks [768, 768+4096)
// pack the mask.  QKV is tensor/issue-bound, maskpack is DRAM-bound -> overlap.
// ---------------------------------------------------------------------------
#define QKV_BLOCKS  (3 * H_ * (N_ / 128))          // 768
#define PACK_BLOCKS (H_ * N_ / 8)                  // 4096

__global__ void __launch_bounds__(256) fused_pre(
    const float* __restrict__ X, const float* __restrict__ WQ,
    const float* __restrict__ WK, const float* __restrict__ WV,
    const int* __restrict__ mask)
{
    if (blockIdx.x < QKV_BLOCKS) {
        const int bx   = blockIdx.x;
        const int tile = bx & 31;            // N_/128 = 32 tiles
        const int which = (bx >> 5) % 3;
        const int h     = bx / 96;
        const float* W = (which == 0) ? WQ : (which == 1) ? WK : WV;
        float* Out = (which == 0) ? g_Q : (which == 1) ? g_K : g_V;
        const float* A = X + (size_t)h * N_ * FIN_ + (size_t)tile * 128 * FIN_;
        gemm_tile_128x64<true>(A, FIN_, W + (size_t)h * HD_ * FIN_, FIN_,
                               Out + (size_t)h * N_ * HD_ + (size_t)tile * 128 * HD_,
                               HD_, FIN_);
    } else {
        const int row  = (blockIdx.x - QKV_BLOCKS) * 8 + (threadIdx.x >> 5);
        const int lane = threadIdx.x & 31;
        const int* mrow = mask + (size_t)row * N_;
        unsigned* orow  = g_maskbits + (size_t)row * NW_;

        for (int c0 = 0; c0 < N_; c0 += 1024) {
            int v[32];
#pragma unroll
            for (int j = 0; j < 32; j++) v[j] = mrow[c0 + j * 32 + lane];
            unsigned word = 0;
#pragma unroll
            for (int j = 0; j < 32; j++) {
                unsigned b = __ballot_sync(0xffffffffu, v[j] != 0);
                if (lane == j) word = b;
            }
            orow[(c0 >> 5) + lane] = word;
        }
    }
}

__global__ void __launch_bounds__(256) oproj_mma(
    const float* __restrict__ WO, float* __restrict__ out)
{
    const int K = H_ * HD_;
    gemm_tile_128x64<false>(g_Hcat + (size_t)blockIdx.x * 128 * K, K,
                            WO + (size_t)blockIdx.y * 64 * K, K,
                            out + (size_t)blockIdx.x * 128 * FOUT_ + blockIdx.y * 64,
                            FOUT_, K);
}

// ---------------------------------------------------------------------------
// Flash attention: cp.async double-buffer, packed mask bits, 2 CTAs/SM,
// ONE __syncthreads per tile (cp.async for t+1 issued after the barrier,
// which jointly guarantees tile-t arrival and other-buffer free).
// ---------------------------------------------------------------------------
#define KSTR  68
#define VSTR  72
#define KWORDS (64 * KSTR)
#define BUFW   (KWORDS + 64 * VSTR)
#define ATTN_SMEM (2 * BUFW * 4)        // 71680 bytes -> 2 CTAs/SM

__global__ void __launch_bounds__(256, 2) attn_mma(void)
{
    extern __shared__ unsigned sm_kv[];
    const int h = blockIdx.y, q0 = blockIdx.x * 128;
    const int tid = threadIdx.x, warp = tid >> 5, lane = tid & 31;
    const int gr = lane >> 2, tc = lane & 3;

    const unsigned sbase = (unsigned)__cvta_generic_to_shared(sm_kv);
    const float* Kh = g_K + (size_t)h * N_ * HD_;
    const float* Vh = g_V + (size_t)h * N_ * HD_;

    const int fr = tid >> 4;
    const int fc = (tid & 15) << 2;

    // cp.async tile 0 -> buffer 0
    {
        unsigned kb = sbase, vb = sbase + KWORDS * 4;
#pragma unroll
        for (int i = 0; i < 4; i++) {
            int r = fr + i * 16;
            cp16(kb + (r * KSTR + fc) * 4, Kh + (size_t)r * 64 + fc);
            cp16(vb + (r * VSTR + fc) * 4, Vh + (size_t)r * 64 + fc);
        }
        asm volatile("cp.async.commit_group;" ::: "memory");
    }

    // Q fragments (tf32-rounded in gmem)
    unsigned qa[8][4];
    {
        const float* Qg = g_Q + ((size_t)h * N_ + q0 + warp * 16) * HD_;
#pragma unroll
        for (int s = 0; s < 8; s++) {
            qa[s][0] = __float_as_uint(Qg[(size_t)gr * 64 + 8 * s + tc]);
            qa[s][1] = __float_as_uint(Qg[(size_t)(gr + 8) * 64 + 8 * s + tc]);
            qa[s][2] = __float_as_uint(Qg[(size_t)gr * 64 + 8 * s + tc + 4]);
            qa[s][3] = __float_as_uint(Qg[(size_t)(gr + 8) * 64 + 8 * s + tc + 4]);
        }
    }

    float O[8][4];
#pragma unroll
    for (int f = 0; f < 8; f++)
#pragma unroll
        for (int j = 0; j < 4; j++) O[f][j] = 0.f;
    float m_lo = -1e30f, m_hi = -1e30f, l_lo = 0.f, l_hi = 0.f;

    // packed mask rows (2 words per 64-key tile, uint2 per row)
    const unsigned* Mrow_lo = g_maskbits + (size_t)(h * N_ + q0 + warp * 16 + gr) * NW_;
    const unsigned* Mrow_hi = Mrow_lo + (size_t)8 * NW_;
    uint2 wl = *(const uint2*)(Mrow_lo);
    uint2 wh = *(const uint2*)(Mrow_hi);

    const int NT = N_ / 64;
    for (int t = 0; t < NT; t++) {
        const int buf = t & 1;

        // tile t landed (committed in previous iteration / prologue)
        asm volatile("cp.async.wait_group 0;" ::: "memory");
        // single barrier: all warps past previous tile's compute AND see tile t
        __syncthreads();

        uint2 nwl, nwh;
        if (t + 1 < NT) {
            const int k1 = (t + 1) * 64;
            const float* Kg = Kh + (size_t)k1 * 64;
            const float* Vg = Vh + (size_t)k1 * 64;
            unsigned kb = sbase + ((buf ^ 1) * BUFW) * 4;
            unsigned vb = kb + KWORDS * 4;
#pragma unroll
            for (int i = 0; i < 4; i++) {
                int r = fr + i * 16;
                cp16(kb + (r * KSTR + fc) * 4, Kg + (size_t)r * 64 + fc);
                cp16(vb + (r * VSTR + fc) * 4, Vg + (size_t)r * 64 + fc);
            }
            asm volatile("cp.async.commit_group;" ::: "memory");
            nwl = *(const uint2*)(Mrow_lo + 2 * (t + 1));
            nwh = *(const uint2*)(Mrow_hi + 2 * (t + 1));
        }

        const unsigned* Ksb = sm_kv + buf * BUFW;
        const unsigned* Vsb = Ksb + KWORDS;

        // S = Q K^T
        float S[8][4];
#pragma unroll
        for (int f = 0; f < 8; f++)
#pragma unroll
            for (int j = 0; j < 4; j++) S[f][j] = 0.f;
#pragma unroll
        for (int s = 0; s < 8; s++) {
#pragma unroll
            for (int f = 0; f < 8; f++) {
                unsigned b0 = Ksb[(8 * f + gr) * KSTR + 8 * s + tc];
                unsigned b1 = Ksb[(8 * f + gr) * KSTR + 8 * s + tc + 4];
                mma8(S[f], qa[s][0], qa[s][1], qa[s][2], qa[s][3], b0, b1);
            }
        }

        // mask (from packed bits) + scale
        const int sh0 = 2 * tc;
#pragma unroll
        for (int f = 0; f < 8; f++) {
            unsigned w_lo = (f < 4) ? wl.x : wl.y;
            unsigned w_hi = (f < 4) ? wh.x : wh.y;
            int sh = ((8 * f) & 31) + sh0;
            S[f][0] = ((w_lo >> sh) & 1)       ? S[f][0] * 0.125f : -1e30f;
            S[f][1] = ((w_lo >> (sh + 1)) & 1) ? S[f][1] * 0.125f : -1e30f;
            S[f][2] = ((w_hi >> sh) & 1)       ? S[f][2] * 0.125f : -1e30f;
            S[f][3] = ((w_hi >> (sh + 1)) & 1) ? S[f][3] * 0.125f : -1e30f;
        }

        // online softmax
        float mx_lo = -1e30f, mx_hi = -1e30f;
#pragma unroll
        for (int f = 0; f < 8; f++) {
            mx_lo = fmaxf(mx_lo, fmaxf(S[f][0], S[f][1]));
            mx_hi = fmaxf(mx_hi, fmaxf(S[f][2], S[f][3]));
        }
#pragma unroll
        for (int off = 1; off <= 2; off <<= 1) {
            mx_lo = fmaxf(mx_lo, __shfl_xor_sync(0xffffffffu, mx_lo, off));
            mx_hi = fmaxf(mx_hi, __shfl_xor_sync(0xffffffffu, mx_hi, off));
        }
        float mn_lo = fmaxf(m_lo, mx_lo), mn_hi = fmaxf(m_hi, mx_hi);
        float corr_lo = __expf(m_lo - mn_lo), corr_hi = __expf(m_hi - mn_hi);
        m_lo = mn_lo; m_hi = mn_hi;

        float ps_lo = 0.f, ps_hi = 0.f;
#pragma unroll
        for (int f = 0; f < 8; f++) {
            S[f][0] = __expf(S[f][0] - mn_lo);
            S[f][1] = __expf(S[f][1] - mn_lo);
            S[f][2] = __expf(S[f][2] - mn_hi);
            S[f][3] = __expf(S[f][3] - mn_hi);
            ps_lo += S[f][0] + S[f][1];
            ps_hi += S[f][2] + S[f][3];
        }
#pragma unroll
        for (int off = 1; off <= 2; off <<= 1) {
            ps_lo += __shfl_xor_sync(0xffffffffu, ps_lo, off);
            ps_hi += __shfl_xor_sync(0xffffffffu, ps_hi, off);
        }
        l_lo = l_lo * corr_lo + ps_lo;
        l_hi = l_hi * corr_hi + ps_hi;
#pragma unroll
        for (int f = 0; f < 8; f++) {
            O[f][0] *= corr_lo; O[f][1] *= corr_lo;
            O[f][2] *= corr_hi; O[f][3] *= corr_hi;
        }

        // PV with in-register shfl transpose
        const int src0 = (lane & ~3) | (tc >> 1);
        const int src2 = src0 + 2;
        const bool oddc = tc & 1;
#pragma unroll
        for (int f = 0; f < 8; f++) {
            float e00 = __shfl_sync(0xffffffffu, S[f][0], src0);
            float e01 = __shfl_sync(0xffffffffu, S[f][1], src0);
            float e20 = __shfl_sync(0xffffffffu, S[f][0], src2);
            float e21 = __shfl_sync(0xffffffffu, S[f][1], src2);
            float e10 = __shfl_sync(0xffffffffu, S[f][2], src0);
            float e11 = __shfl_sync(0xffffffffu, S[f][3], src0);
            float e30 = __shfl_sync(0xffffffffu, S[f][2], src2);
            float e31 = __shfl_sync(0xffffffffu, S[f][3], src2);
            unsigned a0 = f2tf(oddc ? e01 : e00);
            unsigned a2 = f2tf(oddc ? e21 : e20);
            unsigned a1 = f2tf(oddc ? e11 : e10);
            unsigned a3 = f2tf(oddc ? e31 : e30);
#pragma unroll
            for (int g = 0; g < 8; g++) {
                unsigned b0 = Vsb[(8 * f + tc) * VSTR + 8 * g + gr];
                unsigned b1 = Vsb[(8 * f + tc + 4) * VSTR + 8 * g + gr];
                mma8(O[g], a0, a1, a2, a3, b0, b1);
            }
        }

        if (t + 1 < NT) { wl = nwl; wh = nwh; }
    }

    // epilogue
    float il_lo = 1.f / l_lo, il_hi = 1.f / l_hi;
    float* out_lo = g_Hcat + (size_t)(q0 + warp * 16 + gr) * (H_ * HD_) + h * HD_;
    float* out_hi = out_lo + (size_t)8 * (H_ * HD_);
#pragma unroll
    for (int f = 0; f < 8; f++) {
        int col = 8 * f + 2 * tc;
        *(float2*)(out_lo + col) = make_float2(O[f][0] * il_lo, O[f][1] * il_lo);
        *(float2*)(out_hi + col) = make_float2(O[f][2] * il_hi, O[f][3] * il_hi);
    }
}

// ---------------------------------------------------------------------------
extern "C" void kernel_launch(void* const* d_in, const int* in_sizes, int n_in,
                              void* d_out, int out_size) {
    const float* X    = (const float*)d_in[0];
    const int*   mask = (const int*)d_in[1];
    const float* WQ   = (const float*)d_in[2];
    const float* WK   = (const float*)d_in[3];
    const float* WV   = (const float*)d_in[4];
    const float* WO   = (const float*)d_in[5];
    float*       out  = (float*)d_out;

    fused_pre<<<QKV_BLOCKS + PACK_BLOCKS, 256>>>(X, WQ, WK, WV, mask);

    cudaFuncSetAttribute(attn_mma, cudaFuncAttributeMaxDynamicSharedMemorySize,
                         ATTN_SMEM);
    attn_mma<<<dim3(N_ / 128, H_), 256, ATTN_SMEM>>>();

    oproj_mma<<<dim3(N_ / 128, FOUT_ / 64), 256>>>(WO, out);
}